// round 2
// baseline (speedup 1.0000x reference)
#include <cuda_runtime.h>
#include <cuda_bf16.h>

#define RB      4
#define BINS    64      // RB^3
#define BATCH   64
#define CLS     40

// Scratch (alloc-free rule: __device__ globals)
__device__ unsigned g_mn[BATCH * 3];
__device__ unsigned g_mx[BATCH * 3];
__device__ int      g_hist[BATCH * BINS];

// Monotonic float <-> orderable-uint mapping for atomicMin/Max on floats.
__device__ __forceinline__ unsigned f2o(float f) {
    unsigned u = __float_as_uint(f);
    return (u & 0x80000000u) ? ~u : (u | 0x80000000u);
}
__device__ __forceinline__ float o2f(unsigned u) {
    return (u & 0x80000000u) ? __uint_as_float(u & 0x7fffffffu)
                             : __uint_as_float(~u);
}

__global__ void k_init() {
    int t = blockIdx.x * blockDim.x + threadIdx.x;
    if (t < BATCH * 3) { g_mn[t] = 0xFFFFFFFFu; g_mx[t] = 0u; }
    if (t < BATCH * BINS) g_hist[t] = 0;
}

// Pass 1: per-batch per-dim min/max.
// Each iteration handles 4 points = 3 float4s (12 floats == 0 mod 3), so the
// component mapping of the three float4s is fixed:
//   a = (x0,y0,z0,x1)  b = (y1,z1,x2,y2)  c = (z2,x3,y3,z3)
__global__ void k_minmax(const float* __restrict__ x, int nTrip) {
    int bat = blockIdx.y;
    const float4* p = (const float4*)(x + (size_t)bat * (size_t)nTrip * 12);

    float mn0 =  3.402823466e38f, mn1 = mn0, mn2 = mn0;
    float mx0 = -3.402823466e38f, mx1 = mx0, mx2 = mx0;

    for (int i = blockIdx.x * blockDim.x + threadIdx.x; i < nTrip;
         i += gridDim.x * blockDim.x) {
        float4 a = p[3 * i + 0];
        float4 b = p[3 * i + 1];
        float4 c = p[3 * i + 2];
        // comp 0 (x): a.x a.w b.z c.y
        mn0 = fminf(mn0, fminf(fminf(a.x, a.w), fminf(b.z, c.y)));
        mx0 = fmaxf(mx0, fmaxf(fmaxf(a.x, a.w), fmaxf(b.z, c.y)));
        // comp 1 (y): a.y b.x b.w c.z
        mn1 = fminf(mn1, fminf(fminf(a.y, b.x), fminf(b.w, c.z)));
        mx1 = fmaxf(mx1, fmaxf(fmaxf(a.y, b.x), fmaxf(b.w, c.z)));
        // comp 2 (z): a.z b.y c.x c.w
        mn2 = fminf(mn2, fminf(fminf(a.z, b.y), fminf(c.x, c.w)));
        mx2 = fmaxf(mx2, fmaxf(fmaxf(a.z, b.y), fmaxf(c.x, c.w)));
    }

    // Warp reduction
    #pragma unroll
    for (int off = 16; off > 0; off >>= 1) {
        mn0 = fminf(mn0, __shfl_xor_sync(0xffffffffu, mn0, off));
        mn1 = fminf(mn1, __shfl_xor_sync(0xffffffffu, mn1, off));
        mn2 = fminf(mn2, __shfl_xor_sync(0xffffffffu, mn2, off));
        mx0 = fmaxf(mx0, __shfl_xor_sync(0xffffffffu, mx0, off));
        mx1 = fmaxf(mx1, __shfl_xor_sync(0xffffffffu, mx1, off));
        mx2 = fmaxf(mx2, __shfl_xor_sync(0xffffffffu, mx2, off));
    }
    if ((threadIdx.x & 31) == 0) {
        atomicMin(&g_mn[bat * 3 + 0], f2o(mn0));
        atomicMin(&g_mn[bat * 3 + 1], f2o(mn1));
        atomicMin(&g_mn[bat * 3 + 2], f2o(mn2));
        atomicMax(&g_mx[bat * 3 + 0], f2o(mx0));
        atomicMax(&g_mx[bat * 3 + 1], f2o(mx1));
        atomicMax(&g_mx[bat * 3 + 2], f2o(mx2));
    }
}

// Pass 2: per-batch 64-bin histogram with per-warp shared sub-histograms.
__global__ void k_hist(const float* __restrict__ x, int nTrip) {
    __shared__ int sh[8 * BINS];   // 8 warps x 64 bins
    int bat = blockIdx.y;
    for (int i = threadIdx.x; i < 8 * BINS; i += blockDim.x) sh[i] = 0;
    __syncthreads();

    float mn0 = o2f(g_mn[bat * 3 + 0]);
    float mn1 = o2f(g_mn[bat * 3 + 1]);
    float mn2 = o2f(g_mn[bat * 3 + 2]);
    float s0 = 4.0f / (o2f(g_mx[bat * 3 + 0]) - mn0);
    float s1 = 4.0f / (o2f(g_mx[bat * 3 + 1]) - mn1);
    float s2 = 4.0f / (o2f(g_mx[bat * 3 + 2]) - mn2);

    const float4* p = (const float4*)(x + (size_t)bat * (size_t)nTrip * 12);
    int* myh = &sh[(threadIdx.x >> 5) << 6];

    for (int i = blockIdx.x * blockDim.x + threadIdx.x; i < nTrip;
         i += gridDim.x * blockDim.x) {
        float4 a = p[3 * i + 0];
        float4 b = p[3 * i + 1];
        float4 c = p[3 * i + 2];
        // points: (a.x,a.y,a.z) (a.w,b.x,b.y) (b.z,b.w,c.x) (c.y,c.z,c.w)
        float px[4] = {a.x, a.w, b.z, c.y};
        float py[4] = {a.y, b.x, b.w, c.z};
        float pz[4] = {a.z, b.y, c.x, c.w};
        #pragma unroll
        for (int k = 0; k < 4; k++) {
            int i0 = __float2int_rd((px[k] - mn0) * s0);
            int i1 = __float2int_rd((py[k] - mn1) * s1);
            int i2 = __float2int_rd((pz[k] - mn2) * s2);
            i0 = min(RB - 1, max(0, i0));
            i1 = min(RB - 1, max(0, i1));
            i2 = min(RB - 1, max(0, i2));
            atomicAdd(&myh[(i0 << 4) | (i1 << 2) | i2], 1);
        }
    }
    __syncthreads();

    if (threadIdx.x < BINS) {
        int s = 0;
        #pragma unroll
        for (int w = 0; w < 8; w++) s += sh[(w << 6) + threadIdx.x];
        if (s) atomicAdd(&g_hist[bat * BINS + threadIdx.x], s);
    }
}

// Final: out[b, c] = (hist[b,:]/N) @ W[c,:] + bias[c]
__global__ void k_out(const float* __restrict__ W, const float* __restrict__ bias,
                      float* __restrict__ out, float invN) {
    __shared__ float sc[BINS];
    int bat = blockIdx.x;
    int t = threadIdx.x;
    sc[t] = (float)g_hist[bat * BINS + t] * invN;
    __syncthreads();
    if (t < CLS) {
        float acc = bias[t];
        #pragma unroll
        for (int k = 0; k < BINS; k++) acc += sc[k] * W[t * BINS + k];
        out[bat * CLS + t] = acc;
    }
}

extern "C" void kernel_launch(void* const* d_in, const int* in_sizes, int n_in,
                              void* d_out, int out_size) {
    const float* x = (const float*)d_in[0];
    const float* W = (const float*)d_in[1];
    const float* b = (const float*)d_in[2];
    float* out = (float*)d_out;

    int N = in_sizes[0] / (BATCH * 3);   // 100000
    int nTrip = N / 4;                   // 4 points per iteration triple

    k_init<<<(BATCH * BINS + 255) / 256, 256>>>();
    {
        dim3 g(16, BATCH);
        k_minmax<<<g, 256>>>(x, nTrip);
    }
    {
        dim3 g(16, BATCH);
        k_hist<<<g, 256>>>(x, nTrip);
    }
    k_out<<<BATCH, BINS>>>(W, b, out, 1.0f / (float)N);
}

// round 3
// speedup vs baseline: 1.4465x; 1.4465x over previous
#include <cuda_runtime.h>
#include <cuda_bf16.h>
#include <cooperative_groups.h>

namespace cg = cooperative_groups;

#define RB      4
#define BINS    64      // RB^3
#define BATCH   64
#define CLS     40
#define THREADS 1024
#define NWARP   (THREADS / 32)

__global__ void __cluster_dims__(2, 1, 1) __launch_bounds__(THREADS, 1)
k_fused(const float* __restrict__ x, const float* __restrict__ W,
        const float* __restrict__ bias, float* __restrict__ out,
        int N, int nTrip, float invN)
{
    __shared__ float sWt[BINS * CLS];   // W transposed: sWt[k*CLS + c]
    __shared__ int   sh[NWARP * BINS];  // per-warp sub-histograms
    __shared__ float sred[NWARP][6];    // per-warp minmax
    __shared__ float sblk[6];           // this CTA's mn0..2, mx0..2
    __shared__ float sfin[6];           // cluster-combined
    __shared__ int   hfin[BINS];        // this CTA's final hist
    __shared__ float sc[BINS];          // combined counts * invN

    cg::cluster_group cluster = cg::this_cluster();
    const int rank = cluster.block_rank();   // 0 or 1
    const int bat  = blockIdx.y;
    const int tid  = threadIdx.x;
    const int lane = tid & 31, warp = tid >> 5;

    const float*  xb = x + (size_t)bat * 3u * (size_t)N;
    const float4* p  = (const float4*)xb;
    const int half = (nTrip + 1) >> 1;
    const int beg  = rank * half;
    const int end  = min(nTrip, beg + half);
    const int rem  = N - nTrip * 4;          // 0 for N=100000

    // Preload W (transposed) for the epilogue — rank 0 only.
    if (rank == 0) {
        for (int i = tid; i < CLS * BINS; i += THREADS) {
            int c = i >> 6, k = i & 63;
            sWt[k * CLS + c] = W[i];
        }
    }
    // Zero per-warp hists.
    for (int i = tid; i < NWARP * BINS; i += THREADS) sh[i] = 0;

    // ---- Pass 1: min/max over this CTA's half ----
    // 4 points = 3 float4s: a=(x0,y0,z0,x1) b=(y1,z1,x2,y2) c=(z2,x3,y3,z3)
    float mn0 =  3.402823466e38f, mn1 = mn0, mn2 = mn0;
    float mx0 = -3.402823466e38f, mx1 = mx0, mx2 = mx0;
    for (int i = beg + tid; i < end; i += THREADS) {
        float4 a = p[3 * i + 0];
        float4 b = p[3 * i + 1];
        float4 c = p[3 * i + 2];
        mn0 = fminf(mn0, fminf(fminf(a.x, a.w), fminf(b.z, c.y)));
        mx0 = fmaxf(mx0, fmaxf(fmaxf(a.x, a.w), fmaxf(b.z, c.y)));
        mn1 = fminf(mn1, fminf(fminf(a.y, b.x), fminf(b.w, c.z)));
        mx1 = fmaxf(mx1, fmaxf(fmaxf(a.y, b.x), fmaxf(b.w, c.z)));
        mn2 = fminf(mn2, fminf(fminf(a.z, b.y), fminf(c.x, c.w)));
        mx2 = fmaxf(mx2, fmaxf(fmaxf(a.z, b.y), fmaxf(c.x, c.w)));
    }
    // Tail points (N % 4), rank 0 only.
    if (rank == 0 && tid < rem) {
        int j = nTrip * 4 + tid;
        float vx = xb[3 * j + 0], vy = xb[3 * j + 1], vz = xb[3 * j + 2];
        mn0 = fminf(mn0, vx); mx0 = fmaxf(mx0, vx);
        mn1 = fminf(mn1, vy); mx1 = fmaxf(mx1, vy);
        mn2 = fminf(mn2, vz); mx2 = fmaxf(mx2, vz);
    }
    #pragma unroll
    for (int off = 16; off > 0; off >>= 1) {
        mn0 = fminf(mn0, __shfl_xor_sync(0xffffffffu, mn0, off));
        mn1 = fminf(mn1, __shfl_xor_sync(0xffffffffu, mn1, off));
        mn2 = fminf(mn2, __shfl_xor_sync(0xffffffffu, mn2, off));
        mx0 = fmaxf(mx0, __shfl_xor_sync(0xffffffffu, mx0, off));
        mx1 = fmaxf(mx1, __shfl_xor_sync(0xffffffffu, mx1, off));
        mx2 = fmaxf(mx2, __shfl_xor_sync(0xffffffffu, mx2, off));
    }
    if (lane == 0) {
        sred[warp][0] = mn0; sred[warp][1] = mn1; sred[warp][2] = mn2;
        sred[warp][3] = mx0; sred[warp][4] = mx1; sred[warp][5] = mx2;
    }
    __syncthreads();
    if (warp == 0) {   // NWARP == 32: lane l reduces warp l's values
        float v0 = sred[lane][0], v1 = sred[lane][1], v2 = sred[lane][2];
        float v3 = sred[lane][3], v4 = sred[lane][4], v5 = sred[lane][5];
        #pragma unroll
        for (int off = 16; off > 0; off >>= 1) {
            v0 = fminf(v0, __shfl_xor_sync(0xffffffffu, v0, off));
            v1 = fminf(v1, __shfl_xor_sync(0xffffffffu, v1, off));
            v2 = fminf(v2, __shfl_xor_sync(0xffffffffu, v2, off));
            v3 = fmaxf(v3, __shfl_xor_sync(0xffffffffu, v3, off));
            v4 = fmaxf(v4, __shfl_xor_sync(0xffffffffu, v4, off));
            v5 = fmaxf(v5, __shfl_xor_sync(0xffffffffu, v5, off));
        }
        if (lane == 0) {
            sblk[0] = v0; sblk[1] = v1; sblk[2] = v2;
            sblk[3] = v3; sblk[4] = v4; sblk[5] = v5;
        }
    }

    // ---- Cluster exchange of min/max ----
    cluster.sync();
    if (tid < 3) {
        const float* peer = cluster.map_shared_rank(sblk, rank ^ 1);
        sfin[tid]     = fminf(sblk[tid],     peer[tid]);
        sfin[tid + 3] = fmaxf(sblk[tid + 3], peer[tid + 3]);
    }
    __syncthreads();
    const float fm0 = sfin[0], fm1 = sfin[1], fm2 = sfin[2];
    const float s0 = (float)RB / (sfin[3] - fm0);
    const float s1 = (float)RB / (sfin[4] - fm1);
    const float s2 = (float)RB / (sfin[5] - fm2);

    // ---- Pass 2: histogram (per-warp sub-hists) ----
    int* myh = &sh[warp << 6];
    for (int i = beg + tid; i < end; i += THREADS) {
        float4 a = p[3 * i + 0];
        float4 b = p[3 * i + 1];
        float4 c = p[3 * i + 2];
        float px[4] = {a.x, a.w, b.z, c.y};
        float py[4] = {a.y, b.x, b.w, c.z};
        float pz[4] = {a.z, b.y, c.x, c.w};
        #pragma unroll
        for (int k = 0; k < 4; k++) {
            int i0 = __float2int_rd((px[k] - fm0) * s0);
            int i1 = __float2int_rd((py[k] - fm1) * s1);
            int i2 = __float2int_rd((pz[k] - fm2) * s2);
            i0 = min(RB - 1, max(0, i0));
            i1 = min(RB - 1, max(0, i1));
            i2 = min(RB - 1, max(0, i2));
            atomicAdd(&myh[(i0 << 4) | (i1 << 2) | i2], 1);
        }
    }
    if (rank == 0 && tid < rem) {
        int j = nTrip * 4 + tid;
        int i0 = min(RB - 1, max(0, __float2int_rd((xb[3 * j + 0] - fm0) * s0)));
        int i1 = min(RB - 1, max(0, __float2int_rd((xb[3 * j + 1] - fm1) * s1)));
        int i2 = min(RB - 1, max(0, __float2int_rd((xb[3 * j + 2] - fm2) * s2)));
        atomicAdd(&myh[(i0 << 4) | (i1 << 2) | i2], 1);
    }
    __syncthreads();

    // Reduce 32 sub-hists -> hfin[64]
    if (tid < BINS) {
        int s = 0;
        #pragma unroll
        for (int w = 0; w < NWARP; w++) s += sh[(w << 6) + tid];
        hfin[tid] = s;
    }

    // ---- Cluster hist merge + epilogue (rank 0) ----
    cluster.sync();          // hfin ready in both CTAs
    if (rank == 0 && tid < BINS) {
        const int* peer = cluster.map_shared_rank(hfin, 1);
        sc[tid] = (float)(hfin[tid] + peer[tid]) * invN;
    }
    cluster.sync();          // rank 1 may not exit before rank 0 read its smem

    if (rank == 0) {
        __syncthreads();
        if (tid < CLS) {
            float acc = bias[tid];
            #pragma unroll
            for (int k = 0; k < BINS; k++)
                acc = fmaf(sc[k], sWt[k * CLS + tid], acc);
            out[bat * CLS + tid] = acc;
        }
    }
}

extern "C" void kernel_launch(void* const* d_in, const int* in_sizes, int n_in,
                              void* d_out, int out_size) {
    const float* x = (const float*)d_in[0];
    const float* W = (const float*)d_in[1];
    const float* b = (const float*)d_in[2];
    float* out = (float*)d_out;

    int N = in_sizes[0] / (BATCH * 3);   // 100000
    int nTrip = N / 4;

    dim3 grid(2, BATCH);
    k_fused<<<grid, THREADS>>>(x, W, b, out, N, nTrip, 1.0f / (float)N);
}